// round 10
// baseline (speedup 1.0000x reference)
#include <cuda_runtime.h>
#include <cstdint>

#define FULL 0xffffffffu

static constexpr int Tn = 1024;
static constexpr int Kn = 48;
static constexpr int Bn = 512;

__device__ __forceinline__ unsigned long long pack2(float lo, float hi) {
    unsigned long long r;
    asm("mov.b64 %0, {%1, %2};" : "=l"(r) : "f"(lo), "f"(hi));
    return r;
}
__device__ __forceinline__ void unpack2(unsigned long long v, float& lo, float& hi) {
    asm("mov.b64 {%0, %1}, %2;" : "=f"(lo), "=f"(hi) : "l"(v));
}
__device__ __forceinline__ unsigned long long fma2(unsigned long long a, unsigned long long b,
                                                   unsigned long long c) {
    unsigned long long d;
    asm("fma.rn.f32x2 %0, %1, %2, %3;" : "=l"(d) : "l"(a), "l"(b), "l"(c));
    return d;
}
__device__ __forceinline__ unsigned long long add2(unsigned long long a, unsigned long long b) {
    unsigned long long d;
    asm("add.rn.f32x2 %0, %1, %2;" : "=l"(d) : "l"(a), "l"(b));
    return d;
}
__device__ __forceinline__ float rcp_approx(float x) {
    float r;
    asm("rcp.approx.f32 %0, %1;" : "=f"(r) : "f"(x));
    return r;
}

__global__ void _CRF_zero_kernel(float* out) {
    if (threadIdx.x == 0) out[0] = 0.0f;
}

__global__ void __launch_bounds__(64) _CRF_15530601742419_kernel(
    const float* __restrict__ E,            // (B, T, K) emissions
    const int* __restrict__ tags,           // (B, T)
    const void* __restrict__ mask,          // (B, T) bool — layout detected at runtime
    const float* __restrict__ Tr,           // (K, K) transitions
    const float* __restrict__ Sv,           // (K,) start
    const float* __restrict__ Ev,           // (K,) end
    float* __restrict__ out)
{
    __shared__ __align__(16) float sp[2][2][Kn];   // [warp][batchslot][K]

    const int warp = threadIdx.x >> 5;   // 0..1
    const int lane = threadIdx.x & 31;
    const int wg = blockIdx.x * 2 + warp;  // 0..255
    const int bA = wg * 2;
    const int bB = bA + 1;
    const bool vhi = (lane < 16);
    const float* __restrict__ EbA = E + (size_t)bA * Tn * Kn;
    const float* __restrict__ EbB = E + (size_t)bB * Tn * Kn;

    // ---- per-batch: sequence length + gold sequence score ----
    int lenA, lenB;
    float seqA = 0.0f, seqB = 0.0f;   // complete on lane 0
    #pragma unroll 1
    for (int s = 0; s < 2; s++) {
        const int b = bA + s;
        const float* __restrict__ Eb = (s == 0) ? EbA : EbB;
        // length (runtime mask-layout detection)
        int len;
        {
            const unsigned char* mb = (const unsigned char*)mask;
            int si;
            if (mb[1] != 0) {
                const unsigned* mw = (const unsigned*)(mb + (size_t)b * Tn) + lane * 8;
                unsigned sm = 0;
                #pragma unroll
                for (int i = 0; i < 8; i++) sm = __dp4a(mw[i], 0x01010101u, sm);
                si = (int)sm;
            } else {
                const uint4* mw = (const uint4*)((const unsigned*)mask + (size_t)b * Tn) + lane * 8;
                int sm = 0;
                #pragma unroll
                for (int i = 0; i < 8; i++) {
                    uint4 q = mw[i];
                    sm += (q.x != 0) + (q.y != 0) + (q.z != 0) + (q.w != 0);
                }
                si = sm;
            }
            #pragma unroll
            for (int o = 16; o; o >>= 1) si += __shfl_xor_sync(FULL, si, o);
            len = si;
        }
        // gold-path score
        float sc = 0.0f;
        {
            const int* __restrict__ tg = tags + (size_t)b * Tn;
            #pragma unroll 4
            for (int t = lane; t < Tn; t += 32) {
                int tag = tg[t];
                float em = Eb[t * Kn + tag];
                if (t == 0)        sc += Sv[tag] + em;
                else if (t < len)  sc += Tr[tg[t - 1] * Kn + tag] + em;
            }
            #pragma unroll
            for (int o = 16; o; o >>= 1) sc += __shfl_xor_sync(FULL, sc, o);
            if (lane == 0) sc += Ev[tg[len - 1]];
        }
        if (s == 0) { lenA = len; seqA = sc; }
        else        { lenB = len; seqB = sc; }
    }

    // ---- exp(transitions) column pairs into registers (shared by both batches) ----
    unsigned long long Mlo[24], Mhi[24];
    #pragma unroll
    for (int k = 0; k < 24; k++) {
        float a0 = __expf(Tr[(2 * k) * Kn + lane]);
        float a1 = __expf(Tr[(2 * k + 1) * Kn + lane]);
        Mlo[k] = pack2(a0, a1);
        float b0 = 0.0f, b1 = 0.0f;
        if (vhi) {
            b0 = __expf(Tr[(2 * k) * Kn + lane + 32]);
            b1 = __expf(Tr[(2 * k + 1) * Kn + lane + 32]);
        }
        Mhi[k] = pack2(b0, b1);
    }

    // ---- init both recursions: p = exp(score0 - score0[0]), C = score0[0] ----
    float pA_lo, pA_hi, CsA, CcA;
    float pB_lo, pB_hi, CsB, CcB;
    {
        float s_lo = Sv[lane] + EbA[lane];
        float s_hi = vhi ? (Sv[lane + 32] + EbA[lane + 32]) : -1e30f;
        const float s0 = __shfl_sync(FULL, s_lo, 0);
        pA_lo = __expf(s_lo - s0);
        pA_hi = vhi ? __expf(s_hi - s0) : 0.0f;
        CsA = s0; CcA = 0.0f;
    }
    {
        float s_lo = Sv[lane] + EbB[lane];
        float s_hi = vhi ? (Sv[lane + 32] + EbB[lane + 32]) : -1e30f;
        const float s0 = __shfl_sync(FULL, s_lo, 0);
        pB_lo = __expf(s_lo - s0);
        pB_hi = vhi ? __expf(s_hi - s0) : 0.0f;
        CsB = s0; CcB = 0.0f;
    }

    // ---- emission prefetch (raw, distance 2 steps, both batches) ----
    float pfA_lo[2], pfA_hi[2], pfB_lo[2], pfB_hi[2];
    #pragma unroll
    for (int u = 0; u < 2; u++) {
        int t = 1 + u;
        pfA_lo[u] = EbA[t * Kn + lane];
        pfA_hi[u] = vhi ? EbA[t * Kn + lane + 32] : 0.0f;
        pfB_lo[u] = EbB[t * Kn + lane];
        pfB_hi[u] = vhi ? EbB[t * Kn + lane + 32] : 0.0f;
    }

    float* const bufA = sp[warp][0];
    float* const bufB = sp[warp][1];

    // ---- forward recursion: fixed 1024 steps, branch-free body, 2 batches/warp ----
    #pragma unroll 1
    for (int g = 0; g < 512; g++) {
        #pragma unroll
        for (int u = 0; u < 2; u++) {
            const int t = 1 + g * 2 + u;

            // exchange first (one syncwarp covers both buffers)
            bufA[lane] = pA_lo;
            bufB[lane] = pB_lo;
            if (vhi) { bufA[lane + 32] = pA_hi; bufB[lane + 32] = pB_hi; }
            __syncwarp();

            // off-chain: emission exps + prefetch refill (scheduled into sync/LDS shadow)
            const float eemA_lo = __expf(pfA_lo[u]);
            const float eemA_hi = __expf(pfA_hi[u]);
            const float eemB_lo = __expf(pfB_lo[u]);
            const float eemB_hi = __expf(pfB_hi[u]);
            int tp = t + 2; if (tp > Tn - 1) tp = Tn - 1;
            pfA_lo[u] = EbA[tp * Kn + lane];
            pfA_hi[u] = vhi ? EbA[tp * Kn + lane + 32] : 0.0f;
            pfB_lo[u] = EbB[tp * Kn + lane];
            pfB_hi[u] = vhi ? EbB[tp * Kn + lane + 32] : 0.0f;

            // renorm scalars (broadcast LDS, decoupled from fma operands)
            const float p00A = bufA[0];
            const float p00B = bufB[0];
            const float rA   = rcp_approx(p00A);
            const float rB   = rcp_approx(p00B);
            const float lpA  = __logf(p00A);
            const float lpB  = __logf(p00B);
            const float erA_lo = eemA_lo * rA;
            const float erA_hi = eemA_hi * rA;
            const float erB_lo = eemB_lo * rB;
            const float erB_hi = eemB_hi * rB;

            // matvec A (4 accumulators, sequential k)
            const ulonglong2* __restrict__ pbA = (const ulonglong2*)bufA;
            unsigned long long aA0 = 0ull, aA1 = 0ull, bA0 = 0ull, bA1 = 0ull;
            #pragma unroll
            for (int k = 0; k < 12; k++) {
                ulonglong2 q = pbA[k];
                aA0 = fma2(q.x, Mlo[2 * k],     aA0);
                aA1 = fma2(q.y, Mlo[2 * k + 1], aA1);
                bA0 = fma2(q.x, Mhi[2 * k],     bA0);
                bA1 = fma2(q.y, Mhi[2 * k + 1], bA1);
            }
            // matvec B (independent chain; ptxas interleaves with A)
            const ulonglong2* __restrict__ pbB = (const ulonglong2*)bufB;
            unsigned long long aB0 = 0ull, aB1 = 0ull, bB0 = 0ull, bB1 = 0ull;
            #pragma unroll
            for (int k = 0; k < 12; k++) {
                ulonglong2 q = pbB[k];
                aB0 = fma2(q.x, Mlo[2 * k],     aB0);
                aB1 = fma2(q.y, Mlo[2 * k + 1], aB1);
                bB0 = fma2(q.x, Mhi[2 * k],     bB0);
                bB1 = fma2(q.y, Mhi[2 * k + 1], bB1);
            }

            float xA0, xA1, yA0, yA1, xB0, xB1, yB0, yB1;
            unpack2(add2(aA0, aA1), xA0, xA1);
            unpack2(add2(bA0, bA1), yA0, yA1);
            unpack2(add2(aB0, aB1), xB0, xB1);
            unpack2(add2(bB0, bB1), yB0, yB1);

            const float pnA_lo = (xA0 + xA1) * erA_lo;
            const float pnA_hi = (yA0 + yA1) * erA_hi;
            const float pnB_lo = (xB0 + xB1) * erB_lo;
            const float pnB_hi = (yB0 + yB1) * erB_hi;

            // branch-free freeze + Kahan log-offset accumulation (off-chain)
            const bool updA = (t < lenA);
            pA_lo = updA ? pnA_lo : pA_lo;
            pA_hi = updA ? (vhi ? pnA_hi : 0.0f) : pA_hi;
            {
                const float add = updA ? lpA : 0.0f;
                const float y   = add - CcA;
                const float tt  = CsA + y;
                CcA = (tt - CsA) - y;
                CsA = tt;
            }
            const bool updB = (t < lenB);
            pB_lo = updB ? pnB_lo : pB_lo;
            pB_hi = updB ? (vhi ? pnB_hi : 0.0f) : pB_hi;
            {
                const float add = updB ? lpB : 0.0f;
                const float y   = add - CcB;
                const float tt  = CsB + y;
                CcB = (tt - CsB) - y;
                CsB = tt;
            }
        }
    }

    // ---- log_z per batch; single atomic per warp ----
    {
        const float eE_lo = __expf(Ev[lane]);
        const float eE_hi = vhi ? __expf(Ev[lane + 32]) : 0.0f;
        float vA = pA_lo * eE_lo + (vhi ? pA_hi * eE_hi : 0.0f);
        float vB = pB_lo * eE_lo + (vhi ? pB_hi * eE_hi : 0.0f);
        #pragma unroll
        for (int o = 16; o; o >>= 1) {
            vA += __shfl_xor_sync(FULL, vA, o);
            vB += __shfl_xor_sync(FULL, vB, o);
        }
        if (lane == 0) {
            const float lzA = (CsA - CcA) + __logf(vA);
            const float lzB = (CsB - CcB) + __logf(vB);
            atomicAdd(out, ((lzA - seqA) + (lzB - seqB)) * (1.0f / (float)Bn));
        }
    }
}

extern "C" void kernel_launch(void* const* d_in, const int* in_sizes, int n_in,
                              void* d_out, int out_size) {
    const float* E    = (const float*)d_in[0];
    const int*   tags = (const int*)d_in[1];
    const void*  mask = (const void*)d_in[2];
    const float* Tr   = (const float*)d_in[3];
    const float* Sv   = (const float*)d_in[4];
    const float* Ev   = (const float*)d_in[5];
    float* out = (float*)d_out;

    _CRF_zero_kernel<<<1, 32>>>(out);
    _CRF_15530601742419_kernel<<<Bn / 4, 64>>>(E, tags, mask, Tr, Sv, Ev, out);
}